// round 1
// baseline (speedup 1.0000x reference)
#include <cuda_runtime.h>
#include <cuda_bf16.h>
#include <cstdint>

// Problem constants (fixed by the reference)
#define CUBE_L   512
#define EQU_H    1024
#define EQU_W    2048
#define E_COUNT  4
#define CHANNELS 3

// One thread per equirect pixel (h, w). Each thread:
//   - loads uv (float2) + face index once
//   - computes bilinear corner offsets + weights once
//   - gathers 4 taps for each of E*C = 12 planes and writes 12 outputs
// Stores are coalesced along w in every output plane.
__global__ __launch_bounds__(256) void cube2equirec_kernel(
    const float* __restrict__ x,        // (E*6, C, L, L)
    const float* __restrict__ uv,       // (H, W, 2)
    const int*   __restrict__ face_idx, // (H, W)
    float*       __restrict__ out)      // (E, C, H, W)
{
    const int p = blockIdx.x * blockDim.x + threadIdx.x;
    const int NPIX = EQU_H * EQU_W;
    if (p >= NPIX) return;

    // LUT loads (once per pixel)
    const float2 uvp = reinterpret_cast<const float2*>(uv)[p];
    const int f = face_idx[p];

    const float u = uvp.x;
    const float v = uvp.y;

    int x0 = (int)floorf(u);
    int y0 = (int)floorf(v);
    x0 = min(max(x0, 0), CUBE_L - 1);
    y0 = min(max(y0, 0), CUBE_L - 1);
    const int x1 = min(x0 + 1, CUBE_L - 1);
    const int y1 = min(y0 + 1, CUBE_L - 1);

    const float wx = u - (float)x0;
    const float wy = v - (float)y0;
    const float w00 = (1.0f - wx) * (1.0f - wy);
    const float w01 = wx * (1.0f - wy);
    const float w10 = (1.0f - wx) * wy;
    const float w11 = wx * wy;

    const int o00 = y0 * CUBE_L + x0;
    const int o01 = y0 * CUBE_L + x1;
    const int o10 = y1 * CUBE_L + x0;
    const int o11 = y1 * CUBE_L + x1;

    const int plane = CUBE_L * CUBE_L;  // 262144

    #pragma unroll
    for (int e = 0; e < E_COUNT; ++e) {
        const float* __restrict__ face_base =
            x + (size_t)((e * 6 + f) * CHANNELS) * plane;
        #pragma unroll
        for (int c = 0; c < CHANNELS; ++c) {
            const float* __restrict__ b = face_base + (size_t)c * plane;
            const float g00 = __ldg(b + o00);
            const float g01 = __ldg(b + o01);
            const float g10 = __ldg(b + o10);
            const float g11 = __ldg(b + o11);
            const float val = g00 * w00 + g01 * w01 + g10 * w10 + g11 * w11;
            out[(size_t)(e * CHANNELS + c) * NPIX + p] = val;
        }
    }
}

extern "C" void kernel_launch(void* const* d_in, const int* in_sizes, int n_in,
                              void* d_out, int out_size)
{
    const float* x        = (const float*)d_in[0];
    const float* uv       = (const float*)d_in[1];
    const int*   face_idx = (const int*)d_in[2];
    float*       out      = (float*)d_out;

    const int npix = EQU_H * EQU_W;
    const int threads = 256;
    const int blocks = (npix + threads - 1) / threads;
    cube2equirec_kernel<<<blocks, threads>>>(x, uv, face_idx, out);
}